// round 1
// baseline (speedup 1.0000x reference)
#include <cuda_runtime.h>

// Problem constants
#define BATCH   8
#define SEQ     4096
#define EMB     8
#define NQ      (BATCH * SEQ)        // 32768 total queries
#define KSPLIT  4
#define KCHUNK  (SEQ / KSPLIT)       // 1024 keys per block
#define KPAIRS  (KCHUNK / 2)         // 512 key pairs
#define QPB     128                  // queries per block == threads per block

// Scratch (no allocations allowed; __device__ globals are the sanctioned path)
__device__ float g_qkv[NQ * EMB];                 // cos(x + theta), natural layout [B,S,E]
__device__ float g_part[KSPLIT * NQ * 12];        // per-(ksplit,query): acc[8], denom, pad

typedef unsigned long long u64;

// ---- packed f32x2 helpers (sm_100+) ----
__device__ __forceinline__ u64 pack2(float lo, float hi) {
    u64 r; asm("mov.b64 %0, {%1, %2};" : "=l"(r) : "f"(lo), "f"(hi)); return r;
}
__device__ __forceinline__ void unpack2(u64 v, float& lo, float& hi) {
    asm("mov.b64 {%0, %1}, %2;" : "=f"(lo), "=f"(hi) : "l"(v));
}
__device__ __forceinline__ u64 fma2(u64 a, u64 b, u64 c) {
    u64 d; asm("fma.rn.f32x2 %0, %1, %2, %3;" : "=l"(d) : "l"(a), "l"(b), "l"(c)); return d;
}
__device__ __forceinline__ u64 mul2(u64 a, u64 b) {
    u64 d; asm("mul.rn.f32x2 %0, %1, %2;" : "=l"(d) : "l"(a), "l"(b)); return d;
}
__device__ __forceinline__ u64 add2(u64 a, u64 b) {
    u64 d; asm("add.rn.f32x2 %0, %1, %2;" : "=l"(d) : "l"(a), "l"(b)); return d;
}

// ---------------------------------------------------------------------------
// Kernel 1: qkv = cos(x + theta)  (262144 elements, trivial)
// ---------------------------------------------------------------------------
__global__ void k_prep(const float* __restrict__ x, const float* __restrict__ theta) {
    int i = blockIdx.x * blockDim.x + threadIdx.x;
    if (i < NQ * EMB) {
        g_qkv[i] = cosf(x[i] + theta[i & 7]);
    }
}

// ---------------------------------------------------------------------------
// Kernel 2: flash-style attention, no-max single-pass softmax (scores bounded
// by d_k/sqrt(d_k) = 2.83), exp evaluated on the FMA pipe as (poly7(s/4))^4,
// everything packed 2 keys wide in f32x2.
// Partial (acc[8], denom) written per (ksplit, query).
// ---------------------------------------------------------------------------
__global__ void __launch_bounds__(QPB) k_attn() {
    // K tile packed as pairs: smk[pair p][d][slot] ; slot0 = even key, slot1 = odd
    __shared__ __align__(16) float smk[KPAIRS * 16];   // 32 KB

    const int qtile = blockIdx.x;          // 0..255  (32 tiles per batch)
    const int ks    = blockIdx.y;          // 0..KSPLIT-1
    const int b     = qtile >> 5;          // 4096/128 = 32 query tiles per batch
    const int q     = qtile * QPB + threadIdx.x;   // global query index

    // ---- fill smem with this block's 1024-key chunk, pair-interleaved ----
    const float* kbase = g_qkv + ((size_t)b * SEQ + (size_t)ks * KCHUNK) * EMB;
    for (int t = threadIdx.x; t < KCHUNK; t += QPB) {
        float4 a = *(const float4*)(kbase + (size_t)t * 8);
        float4 c = *(const float4*)(kbase + (size_t)t * 8 + 4);
        float* dst = smk + (t >> 1) * 16 + (t & 1);
        dst[0]  = a.x; dst[2]  = a.y; dst[4]  = a.z; dst[6]  = a.w;
        dst[8]  = c.x; dst[10] = c.y; dst[12] = c.z; dst[14] = c.w;
    }
    __syncthreads();

    // ---- per-thread query, pre-scaled by 1/(4*sqrt(8)) so dot == s/4 ----
    const float SCALE = 0.08838834764831845f;  // 1/(4*sqrt(8))
    const float4* q4 = (const float4*)(g_qkv + (size_t)q * 8);
    float4 qa = q4[0], qb = q4[1];
    float qs[8] = {qa.x, qa.y, qa.z, qa.w, qb.x, qb.y, qb.z, qb.w};
    u64 qq[8];
#pragma unroll
    for (int d = 0; d < 8; ++d) {
        float v = qs[d] * SCALE;
        qq[d] = pack2(v, v);
    }

    // exp(u*4) = (poly7(u))^4, u in [-0.708, 0.708], Taylor coeffs 1/i!
    const u64 C7  = pack2(1.9841269841e-4f, 1.9841269841e-4f);   // 1/5040
    const u64 C6  = pack2(1.3888888889e-3f, 1.3888888889e-3f);   // 1/720
    const u64 C5  = pack2(8.3333333333e-3f, 8.3333333333e-3f);   // 1/120
    const u64 C4  = pack2(4.1666666667e-2f, 4.1666666667e-2f);   // 1/24
    const u64 C3  = pack2(1.6666666667e-1f, 1.6666666667e-1f);   // 1/6
    const u64 C2  = pack2(0.5f, 0.5f);
    const u64 ONE = pack2(1.0f, 1.0f);

    u64 acc0 = 0, acc1 = 0, acc2 = 0, acc3 = 0;
    u64 acc4 = 0, acc5 = 0, acc6 = 0, acc7 = 0;
    u64 den  = 0;

#pragma unroll 2
    for (int p = 0; p < KPAIRS; ++p) {
        const ulonglong2* sp = (const ulonglong2*)smk + (size_t)p * 4;
        ulonglong2 v0 = sp[0], v1 = sp[1], v2 = sp[2], v3 = sp[3];
        u64 k0 = v0.x, k1 = v0.y, k2 = v1.x, k3 = v1.y;
        u64 k4 = v2.x, k5 = v2.y, k6 = v3.x, k7 = v3.y;

        // packed dot: (s_even, s_odd)/4   (two balanced chains for ILP)
        u64 sa = mul2(qq[0], k0);
        sa = fma2(qq[1], k1, sa);
        sa = fma2(qq[2], k2, sa);
        sa = fma2(qq[3], k3, sa);
        u64 sb = mul2(qq[4], k4);
        sb = fma2(qq[5], k5, sb);
        sb = fma2(qq[6], k6, sb);
        sb = fma2(qq[7], k7, sb);
        u64 u = add2(sa, sb);

        // w = exp(4u): Horner degree-7 then square twice
        u64 w = fma2(C7, u, C6);
        w = fma2(w, u, C5);
        w = fma2(w, u, C4);
        w = fma2(w, u, C3);
        w = fma2(w, u, C2);
        w = fma2(w, u, ONE);
        w = fma2(w, u, ONE);
        w = mul2(w, w);
        w = mul2(w, w);

        // V accumulate (v == k) + denominator
        acc0 = fma2(k0, w, acc0);
        acc1 = fma2(k1, w, acc1);
        acc2 = fma2(k2, w, acc2);
        acc3 = fma2(k3, w, acc3);
        acc4 = fma2(k4, w, acc4);
        acc5 = fma2(k5, w, acc5);
        acc6 = fma2(k6, w, acc6);
        acc7 = fma2(k7, w, acc7);
        den  = add2(den, w);
    }

    // ---- reduce packed halves, write partial ----
    float* out = g_part + ((size_t)ks * NQ + q) * 12;
    u64 accs[8] = {acc0, acc1, acc2, acc3, acc4, acc5, acc6, acc7};
    float lo, hi;
#pragma unroll
    for (int d = 0; d < 8; ++d) {
        unpack2(accs[d], lo, hi);
        out[d] = lo + hi;
    }
    unpack2(den, lo, hi);
    out[8] = lo + hi;
}

// ---------------------------------------------------------------------------
// Kernel 3: combine ksplit partials, normalize, apply W_out^T
// ---------------------------------------------------------------------------
__global__ void k_fin(const float* __restrict__ W, float* __restrict__ out) {
    __shared__ float sw[64];
    if (threadIdx.x < 64) sw[threadIdx.x] = W[threadIdx.x];
    __syncthreads();

    int q = blockIdx.x * blockDim.x + threadIdx.x;
    if (q >= NQ) return;

    float acc[8] = {0, 0, 0, 0, 0, 0, 0, 0};
    float den = 0.0f;
#pragma unroll
    for (int ks = 0; ks < KSPLIT; ++ks) {
        const float* p = g_part + ((size_t)ks * NQ + q) * 12;
#pragma unroll
        for (int d = 0; d < 8; ++d) acc[d] += p[d];
        den += p[8];
    }
    float inv = 1.0f / den;
    float o[8];
#pragma unroll
    for (int d = 0; d < 8; ++d) o[d] = acc[d] * inv;

#pragma unroll
    for (int e = 0; e < 8; ++e) {
        float s = 0.0f;
#pragma unroll
        for (int d = 0; d < 8; ++d) s = fmaf(o[d], sw[e * 8 + d], s);
        out[(size_t)q * 8 + e] = s;
    }
}

// ---------------------------------------------------------------------------
extern "C" void kernel_launch(void* const* d_in, const int* in_sizes, int n_in,
                              void* d_out, int out_size) {
    const float* x     = (const float*)d_in[0];   // [8,4096,8] f32
    const float* theta = (const float*)d_in[1];   // [8] f32
    const float* W_out = (const float*)d_in[2];   // [8,8] f32
    float* out = (float*)d_out;                   // [8,4096,8] f32

    k_prep<<<(NQ * EMB + 255) / 256, 256>>>(x, theta);
    k_attn<<<dim3(NQ / QPB, KSPLIT), QPB>>>();
    k_fin<<<(NQ + 255) / 256, 256>>>(W_out, out);
}

// round 2
// speedup vs baseline: 1.0619x; 1.0619x over previous
#include <cuda_runtime.h>

// Problem constants
#define BATCH   8
#define SEQ     4096
#define EMB     8
#define NQ      (BATCH * SEQ)        // 32768 total queries
#define KSPLIT  4
#define KCHUNK  (SEQ / KSPLIT)       // 1024 keys per block
#define KPAIRS  (KCHUNK / 2)         // 512 key pairs
#define QPB     128                  // queries per block == threads per block

// Scratch (no allocations allowed; __device__ globals are the sanctioned path)
__device__ float g_qkv[NQ * EMB];                 // cos(x + theta), natural layout [B,S,E]
__device__ float g_part[KSPLIT * NQ * 12];        // per-(ksplit,query): acc[8], denom, pad

typedef unsigned long long u64;

// ---- packed f32x2 helpers (sm_100+) ----
__device__ __forceinline__ u64 pack2(float lo, float hi) {
    u64 r; asm("mov.b64 %0, {%1, %2};" : "=l"(r) : "f"(lo), "f"(hi)); return r;
}
__device__ __forceinline__ void unpack2(u64 v, float& lo, float& hi) {
    asm("mov.b64 {%0, %1}, %2;" : "=f"(lo), "=f"(hi) : "l"(v));
}
__device__ __forceinline__ u64 fma2(u64 a, u64 b, u64 c) {
    u64 d; asm("fma.rn.f32x2 %0, %1, %2, %3;" : "=l"(d) : "l"(a), "l"(b), "l"(c)); return d;
}
__device__ __forceinline__ u64 mul2(u64 a, u64 b) {
    u64 d; asm("mul.rn.f32x2 %0, %1, %2;" : "=l"(d) : "l"(a), "l"(b)); return d;
}
__device__ __forceinline__ u64 add2(u64 a, u64 b) {
    u64 d; asm("add.rn.f32x2 %0, %1, %2;" : "=l"(d) : "l"(a), "l"(b)); return d;
}

// ---------------------------------------------------------------------------
// Kernel 1: qkv = cos(x + theta)  (262144 elements, trivial)
// ---------------------------------------------------------------------------
__global__ void k_prep(const float* __restrict__ x, const float* __restrict__ theta) {
    int i = blockIdx.x * blockDim.x + threadIdx.x;
    if (i < NQ * EMB) {
        g_qkv[i] = cosf(x[i] + theta[i & 7]);
    }
}

// ---------------------------------------------------------------------------
// Kernel 2: flash-style attention, no-max single-pass softmax (|s| <= 2.83),
// exp on the FMA pipe as (poly5(s/4))^4 with Chebyshev-economized deg-5 poly,
// everything packed 2 keys wide in f32x2. 24 packed fma-pipe ops / key pair.
// ---------------------------------------------------------------------------
__global__ void __launch_bounds__(QPB) k_attn() {
    // K tile packed as pairs: smk[pair p][d][slot] ; slot0 = even key, slot1 = odd
    __shared__ __align__(16) float smk[KPAIRS * 16];   // 32 KB

    const int qtile = blockIdx.x;          // 0..255  (32 tiles per batch)
    const int ks    = blockIdx.y;          // 0..KSPLIT-1
    const int b     = qtile >> 5;          // 4096/128 = 32 query tiles per batch
    const int q     = qtile * QPB + threadIdx.x;   // global query index

    // ---- fill smem with this block's 1024-key chunk, pair-interleaved ----
    const float* kbase = g_qkv + ((size_t)b * SEQ + (size_t)ks * KCHUNK) * EMB;
    for (int t = threadIdx.x; t < KCHUNK; t += QPB) {
        float4 a = *(const float4*)(kbase + (size_t)t * 8);
        float4 c = *(const float4*)(kbase + (size_t)t * 8 + 4);
        float* dst = smk + (t >> 1) * 16 + (t & 1);
        dst[0]  = a.x; dst[2]  = a.y; dst[4]  = a.z; dst[6]  = a.w;
        dst[8]  = c.x; dst[10] = c.y; dst[12] = c.z; dst[14] = c.w;
    }
    __syncthreads();

    // ---- per-thread query, pre-scaled by 1/(4*sqrt(8)) so dot == s/4 ----
    const float SCALE = 0.08838834764831845f;  // 1/(4*sqrt(8))
    const float4* q4 = (const float4*)(g_qkv + (size_t)q * 8);
    float4 qa = q4[0], qb = q4[1];
    float qs[8] = {qa.x, qa.y, qa.z, qa.w, qb.x, qb.y, qb.z, qb.w};
    u64 qq[8];
#pragma unroll
    for (int d = 0; d < 8; ++d) {
        float v = qs[d] * SCALE;
        qq[d] = pack2(v, v);
    }

    // exp(4u) = (p(u))^4, u in [-0.7072, 0.7072].
    // p = Chebyshev-economized degree-5 approx of e^u on that interval
    // (deg-7 Taylor with T6,T7 folded down); |p - e^u| ~ 6e-6.
    const u64 C5 = pack2(8.506967e-3f, 8.506967e-3f);
    const u64 C4 = pack2(4.2708333e-2f, 4.2708333e-2f);
    const u64 C3 = pack2(1.6662326e-1f, 1.6662326e-1f);
    const u64 C2 = pack2(4.9980469e-1f, 4.9980469e-1f);
    const u64 C1 = pack2(1.0000027f, 1.0000027f);
    const u64 C0 = pack2(1.0000054f, 1.0000054f);

    u64 acc0 = 0, acc1 = 0, acc2 = 0, acc3 = 0;
    u64 acc4 = 0, acc5 = 0, acc6 = 0, acc7 = 0;
    u64 den  = 0;

#pragma unroll 2
    for (int p = 0; p < KPAIRS; ++p) {
        const ulonglong2* sp = (const ulonglong2*)smk + (size_t)p * 4;
        ulonglong2 v0 = sp[0], v1 = sp[1], v2 = sp[2], v3 = sp[3];
        u64 k0 = v0.x, k1 = v0.y, k2 = v1.x, k3 = v1.y;
        u64 k4 = v2.x, k5 = v2.y, k6 = v3.x, k7 = v3.y;

        // packed dot, single chain: u = (s_even, s_odd)/4   (8 ops)
        u64 u = mul2(qq[0], k0);
        u = fma2(qq[1], k1, u);
        u = fma2(qq[2], k2, u);
        u = fma2(qq[3], k3, u);
        u = fma2(qq[4], k4, u);
        u = fma2(qq[5], k5, u);
        u = fma2(qq[6], k6, u);
        u = fma2(qq[7], k7, u);

        // w = exp(4u): deg-5 Horner then square twice   (7 ops)
        u64 w = fma2(C5, u, C4);
        w = fma2(w, u, C3);
        w = fma2(w, u, C2);
        w = fma2(w, u, C1);
        w = fma2(w, u, C0);
        w = mul2(w, w);
        w = mul2(w, w);

        // V accumulate (v == k) + denominator   (9 ops)
        acc0 = fma2(k0, w, acc0);
        acc1 = fma2(k1, w, acc1);
        acc2 = fma2(k2, w, acc2);
        acc3 = fma2(k3, w, acc3);
        acc4 = fma2(k4, w, acc4);
        acc5 = fma2(k5, w, acc5);
        acc6 = fma2(k6, w, acc6);
        acc7 = fma2(k7, w, acc7);
        den  = add2(den, w);
    }

    // ---- reduce packed halves, write partial ----
    float* out = g_part + ((size_t)ks * NQ + q) * 12;
    u64 accs[8] = {acc0, acc1, acc2, acc3, acc4, acc5, acc6, acc7};
    float lo, hi;
#pragma unroll
    for (int d = 0; d < 8; ++d) {
        unpack2(accs[d], lo, hi);
        out[d] = lo + hi;
    }
    unpack2(den, lo, hi);
    out[8] = lo + hi;
}

// ---------------------------------------------------------------------------
// Kernel 3: combine ksplit partials, normalize, apply W_out^T
// ---------------------------------------------------------------------------
__global__ void k_fin(const float* __restrict__ W, float* __restrict__ out) {
    __shared__ float sw[64];
    if (threadIdx.x < 64) sw[threadIdx.x] = W[threadIdx.x];
    __syncthreads();

    int q = blockIdx.x * blockDim.x + threadIdx.x;
    if (q >= NQ) return;

    float acc[8] = {0, 0, 0, 0, 0, 0, 0, 0};
    float den = 0.0f;
#pragma unroll
    for (int ks = 0; ks < KSPLIT; ++ks) {
        const float* p = g_part + ((size_t)ks * NQ + q) * 12;
#pragma unroll
        for (int d = 0; d < 8; ++d) acc[d] += p[d];
        den += p[8];
    }
    float inv = 1.0f / den;
    float o[8];
#pragma unroll
    for (int d = 0; d < 8; ++d) o[d] = acc[d] * inv;

#pragma unroll
    for (int e = 0; e < 8; ++e) {
        float s = 0.0f;
#pragma unroll
        for (int d = 0; d < 8; ++d) s = fmaf(o[d], sw[e * 8 + d], s);
        out[(size_t)q * 8 + e] = s;
    }
}

// ---------------------------------------------------------------------------
extern "C" void kernel_launch(void* const* d_in, const int* in_sizes, int n_in,
                              void* d_out, int out_size) {
    const float* x     = (const float*)d_in[0];   // [8,4096,8] f32
    const float* theta = (const float*)d_in[1];   // [8] f32
    const float* W_out = (const float*)d_in[2];   // [8,8] f32
    float* out = (float*)d_out;                   // [8,4096,8] f32

    k_prep<<<(NQ * EMB + 255) / 256, 256>>>(x, theta);
    k_attn<<<dim3(NQ / QPB, KSPLIT), QPB>>>();
    k_fin<<<(NQ + 255) / 256, 256>>>(W_out, out);
}

// round 3
// speedup vs baseline: 1.1396x; 1.0732x over previous
#include <cuda_runtime.h>

// Problem constants
#define BATCH   8
#define SEQ     4096
#define EMB     8
#define NQ      (BATCH * SEQ)        // 32768 total queries
#define KSPLIT  4
#define KCHUNK  (SEQ / KSPLIT)       // 1024 keys per block
#define KPAIRS  (KCHUNK / 2)         // 512 key pairs
#define QPB     128                  // queries per block == threads per block

// Scratch (no allocations allowed; __device__ globals are the sanctioned path)
__device__ float g_qkv[NQ * EMB];                 // cos(x + theta), natural layout [B,S,E]
__device__ float g_part[KSPLIT * NQ * 12];        // per-(ksplit,query): acc[8], denom, pad

typedef unsigned long long u64;

// ---- packed f32x2 helpers (sm_100+) ----
__device__ __forceinline__ u64 pack2(float lo, float hi) {
    u64 r; asm("mov.b64 %0, {%1, %2};" : "=l"(r) : "f"(lo), "f"(hi)); return r;
}
__device__ __forceinline__ void unpack2(u64 v, float& lo, float& hi) {
    asm("mov.b64 {%0, %1}, %2;" : "=f"(lo), "=f"(hi) : "l"(v));
}
__device__ __forceinline__ u64 fma2(u64 a, u64 b, u64 c) {
    u64 d; asm("fma.rn.f32x2 %0, %1, %2, %3;" : "=l"(d) : "l"(a), "l"(b), "l"(c)); return d;
}
__device__ __forceinline__ u64 mul2(u64 a, u64 b) {
    u64 d; asm("mul.rn.f32x2 %0, %1, %2;" : "=l"(d) : "l"(a), "l"(b)); return d;
}
__device__ __forceinline__ u64 add2(u64 a, u64 b) {
    u64 d; asm("add.rn.f32x2 %0, %1, %2;" : "=l"(d) : "l"(a), "l"(b)); return d;
}
__device__ __forceinline__ float ex2f(float x) {
    float r; asm("ex2.approx.f32 %0, %1;" : "=f"(r) : "f"(x)); return r;
}

// ---------------------------------------------------------------------------
// Kernel 1: qkv = cos(x + theta). One row (8 floats) per thread, vectorized.
// ---------------------------------------------------------------------------
__global__ void k_prep(const float* __restrict__ x, const float* __restrict__ theta) {
    int r = blockIdx.x * blockDim.x + threadIdx.x;   // row index (query)
    if (r >= NQ) return;
    float t0 = theta[0], t1 = theta[1], t2 = theta[2], t3 = theta[3];
    float t4 = theta[4], t5 = theta[5], t6 = theta[6], t7 = theta[7];
    const float4* xp = (const float4*)(x + (size_t)r * 8);
    float4 a = xp[0], b = xp[1];
    float4 oa, ob;
    oa.x = __cosf(a.x + t0); oa.y = __cosf(a.y + t1);
    oa.z = __cosf(a.z + t2); oa.w = __cosf(a.w + t3);
    ob.x = __cosf(b.x + t4); ob.y = __cosf(b.y + t5);
    ob.z = __cosf(b.z + t6); ob.w = __cosf(b.w + t7);
    float4* op = (float4*)(g_qkv + (size_t)r * 8);
    op[0] = oa; op[1] = ob;
}

// ---------------------------------------------------------------------------
// Kernel 2: flash-style attention, no-max single-pass softmax (|s| <= 2.83).
// exp moved to the idle MUFU pipe: dot chain directly produces s*log2(e)
// (scale folded into q), then w = ex2() per packed half. 17 packed fma-pipe
// ops + 2 MUFU per key pair (was 24 fma ops).
// ---------------------------------------------------------------------------
__global__ void __launch_bounds__(QPB) k_attn() {
    // K tile packed as pairs: smk[pair p][d][slot] ; slot0 = even key, slot1 = odd
    __shared__ __align__(16) float smk[KPAIRS * 16];   // 32 KB

    const int qtile = blockIdx.x;          // 0..255  (32 tiles per batch)
    const int ks    = blockIdx.y;          // 0..KSPLIT-1
    const int b     = qtile >> 5;          // 32 query tiles per batch
    const int q     = qtile * QPB + threadIdx.x;   // global query index

    // ---- fill smem with this block's 1024-key chunk, pair-interleaved ----
    // Each thread handles whole pairs: loads keys 2t,2t+1 and writes float2s.
    const float* kbase = g_qkv + ((size_t)b * SEQ + (size_t)ks * KCHUNK) * EMB;
    for (int p = threadIdx.x; p < KPAIRS; p += QPB) {
        const float4* e4 = (const float4*)(kbase + (size_t)(2 * p) * 8);
        float4 e0 = e4[0], e1 = e4[1];     // even key
        float4 o0 = e4[2], o1 = e4[3];     // odd key
        float2* dst = (float2*)(smk + p * 16);
        dst[0] = make_float2(e0.x, o0.x);
        dst[1] = make_float2(e0.y, o0.y);
        dst[2] = make_float2(e0.z, o0.z);
        dst[3] = make_float2(e0.w, o0.w);
        dst[4] = make_float2(e1.x, o1.x);
        dst[5] = make_float2(e1.y, o1.y);
        dst[6] = make_float2(e1.z, o1.z);
        dst[7] = make_float2(e1.w, o1.w);
    }
    __syncthreads();

    // ---- per-thread query, pre-scaled by log2(e)/sqrt(8):
    //      dot yields s*log2(e) directly, so w = ex2(dot). ----
    const float SCALE = 0.51006310094284079f;  // log2(e)/sqrt(8)
    const float4* q4 = (const float4*)(g_qkv + (size_t)q * 8);
    float4 qa = q4[0], qb = q4[1];
    float qs[8] = {qa.x, qa.y, qa.z, qa.w, qb.x, qb.y, qb.z, qb.w};
    u64 qq[8];
#pragma unroll
    for (int d = 0; d < 8; ++d) {
        float v = qs[d] * SCALE;
        qq[d] = pack2(v, v);
    }

    u64 acc0 = 0, acc1 = 0, acc2 = 0, acc3 = 0;
    u64 acc4 = 0, acc5 = 0, acc6 = 0, acc7 = 0;
    u64 den  = 0;

#pragma unroll 2
    for (int p = 0; p < KPAIRS; ++p) {
        const ulonglong2* sp = (const ulonglong2*)smk + (size_t)p * 4;
        ulonglong2 v0 = sp[0], v1 = sp[1], v2 = sp[2], v3 = sp[3];
        u64 k0 = v0.x, k1 = v0.y, k2 = v1.x, k3 = v1.y;
        u64 k4 = v2.x, k5 = v2.y, k6 = v3.x, k7 = v3.y;

        // packed dot, single chain: u = (s_even, s_odd)*log2(e)   (8 fma ops)
        u64 u = mul2(qq[0], k0);
        u = fma2(qq[1], k1, u);
        u = fma2(qq[2], k2, u);
        u = fma2(qq[3], k3, u);
        u = fma2(qq[4], k4, u);
        u = fma2(qq[5], k5, u);
        u = fma2(qq[6], k6, u);
        u = fma2(qq[7], k7, u);

        // w = 2^u per half on the MUFU pipe (idle otherwise)
        float ulo, uhi;
        unpack2(u, ulo, uhi);
        u64 w = pack2(ex2f(ulo), ex2f(uhi));

        // V accumulate (v == k) + denominator   (9 fma ops)
        acc0 = fma2(k0, w, acc0);
        acc1 = fma2(k1, w, acc1);
        acc2 = fma2(k2, w, acc2);
        acc3 = fma2(k3, w, acc3);
        acc4 = fma2(k4, w, acc4);
        acc5 = fma2(k5, w, acc5);
        acc6 = fma2(k6, w, acc6);
        acc7 = fma2(k7, w, acc7);
        den  = add2(den, w);
    }

    // ---- reduce packed halves, write partial ----
    float* out = g_part + ((size_t)ks * NQ + q) * 12;
    u64 accs[8] = {acc0, acc1, acc2, acc3, acc4, acc5, acc6, acc7};
    float lo, hi;
    float res[8];
#pragma unroll
    for (int d = 0; d < 8; ++d) {
        unpack2(accs[d], lo, hi);
        res[d] = lo + hi;
    }
    ((float4*)out)[0] = make_float4(res[0], res[1], res[2], res[3]);
    ((float4*)out)[1] = make_float4(res[4], res[5], res[6], res[7]);
    unpack2(den, lo, hi);
    out[8] = lo + hi;
}

// ---------------------------------------------------------------------------
// Kernel 3: combine ksplit partials, normalize, apply W_out^T
// ---------------------------------------------------------------------------
__global__ void k_fin(const float* __restrict__ W, float* __restrict__ out) {
    __shared__ float sw[64];
    if (threadIdx.x < 64) sw[threadIdx.x] = W[threadIdx.x];
    __syncthreads();

    int q = blockIdx.x * blockDim.x + threadIdx.x;
    if (q >= NQ) return;

    float acc[8] = {0, 0, 0, 0, 0, 0, 0, 0};
    float den = 0.0f;
#pragma unroll
    for (int ks = 0; ks < KSPLIT; ++ks) {
        const float* p = g_part + ((size_t)ks * NQ + q) * 12;
        float4 pa = ((const float4*)p)[0];
        float4 pb = ((const float4*)p)[1];
        acc[0] += pa.x; acc[1] += pa.y; acc[2] += pa.z; acc[3] += pa.w;
        acc[4] += pb.x; acc[5] += pb.y; acc[6] += pb.z; acc[7] += pb.w;
        den += p[8];
    }
    float inv = 1.0f / den;
    float o[8];
#pragma unroll
    for (int d = 0; d < 8; ++d) o[d] = acc[d] * inv;

    float r[8];
#pragma unroll
    for (int e = 0; e < 8; ++e) {
        float s = 0.0f;
#pragma unroll
        for (int d = 0; d < 8; ++d) s = fmaf(o[d], sw[e * 8 + d], s);
        r[e] = s;
    }
    float4* op = (float4*)(out + (size_t)q * 8);
    op[0] = make_float4(r[0], r[1], r[2], r[3]);
    op[1] = make_float4(r[4], r[5], r[6], r[7]);
}

// ---------------------------------------------------------------------------
extern "C" void kernel_launch(void* const* d_in, const int* in_sizes, int n_in,
                              void* d_out, int out_size) {
    const float* x     = (const float*)d_in[0];   // [8,4096,8] f32
    const float* theta = (const float*)d_in[1];   // [8] f32
    const float* W_out = (const float*)d_in[2];   // [8,8] f32
    float* out = (float*)d_out;                   // [8,4096,8] f32

    k_prep<<<(NQ + 255) / 256, 256>>>(x, theta);
    k_attn<<<dim3(NQ / QPB, KSPLIT), QPB>>>();
    k_fin<<<(NQ + 255) / 256, 256>>>(W_out, out);
}